// round 16
// baseline (speedup 1.0000x reference)
// SpectralCapsules R16: R15 (shared-scalar sd/se/stau, zero-branch zero-shfl
// hot loop) with the QR deflation scan reduction fixed: highest stopping lane
// (31-__clz), matching LAPACK's top-down M scan. k1a unchanged.
#include <cuda_runtime.h>
#include <math.h>

#define FULLMASK 0xffffffffu

constexpr int Bb = 16;    // batch
constexpr int Mm = 256;   // H*W
constexpr int Cc = 544;   // channels = L*(P+1)

__device__ float g_Sp[Bb * 32 * 4 * 256]; // partial S per m-chunk

// ---------------------------------------------------------------------------
// K1a: partial S over 64 m per block (unchanged R8).
// ---------------------------------------------------------------------------
__global__ void __launch_bounds__(256) k1a(const float* __restrict__ in) {
    int blk = blockIdx.x;               // ((b*32+l)*4 + chunk)
    int chunk = blk & 3;
    int bl = blk >> 2;
    int b = bl >> 5, l = bl & 31;
    __shared__ float sp[64 * 16];
    __shared__ float sa2[64];
    __shared__ float red[4][16 * 17];
    int t = threadIdx.x;
    const float* base = in + (size_t)b * Mm * Cc + (size_t)chunk * 64 * Cc;
    {
        int mm = t >> 2, q = t & 3;
        const float4* src = (const float4*)(base + (size_t)mm * Cc + l * 16) + q;
        ((float4*)sp)[mm * 4 + q] = *src;
    }
    if (t < 64) {
        float a = base[(size_t)t * Cc + 512 + l];
        sa2[t] = a * a;
    }
    __syncthreads();
    int g = t >> 6, u = t & 63;
    int r0 = (u >> 3) * 2, c0 = (u & 7) * 2;
    float a00 = 0.f, a01 = 0.f, a10 = 0.f, a11 = 0.f;
#pragma unroll
    for (int mm = 0; mm < 16; ++mm) {
        int m = g * 16 + mm;
        float a2 = sa2[m];
        float2 vr = *(const float2*)&sp[m * 16 + r0];
        float2 vc = *(const float2*)&sp[m * 16 + c0];
        float t0 = a2 * vr.x, t1 = a2 * vr.y;
        a00 = fmaf(t0, vc.x, a00);
        a01 = fmaf(t0, vc.y, a01);
        a10 = fmaf(t1, vc.x, a10);
        a11 = fmaf(t1, vc.y, a11);
    }
    red[g][r0 * 17 + c0]           = a00;
    red[g][r0 * 17 + c0 + 1]       = a01;
    red[g][(r0 + 1) * 17 + c0]     = a10;
    red[g][(r0 + 1) * 17 + c0 + 1] = a11;
    __syncthreads();
    {
        int r = t >> 4, c = t & 15;
        int idx = r * 17 + c;
        g_Sp[blk * 256 + t] = ((red[0][idx] + red[1][idx]) + red[2][idx]) + red[3][idx];
    }
}

// ---------------------------------------------------------------------------
// helpers
// ---------------------------------------------------------------------------
__device__ __forceinline__ float wsum(float x) {
#pragma unroll
    for (int o = 16; o; o >>= 1) x += __shfl_xor_sync(FULLMASK, x, o);
    return x;
}
__device__ __forceinline__ float wmaxf(float x) {
#pragma unroll
    for (int o = 16; o; o >>= 1) x = fmaxf(x, __shfl_xor_sync(FULLMASK, x, o));
    return x;
}
__device__ __forceinline__ float sget(float v, int i) {
    return __shfl_sync(FULLMASK, v, i);
}

__device__ __forceinline__ void lartg(float f, float g, float& c, float& s, float& r) {
    if (g == 0.f)      { c = 1.f; s = 0.f; r = f; }
    else if (f == 0.f) { c = 0.f; s = copysignf(1.f, g); r = fabsf(g); }
    else {
        float t2 = fmaf(f, f, g * g);
        float rinv = rsqrtf(t2);
        float d = t2 * rinv;
        c = fabsf(f) * rinv;
        r = copysignf(d, f);
        s = g * rinv * copysignf(1.f, f);
    }
}

__device__ __forceinline__ void laev2(float a, float b, float c,
                                      float& rt1, float& rt2, float& cs1, float& sn1) {
    float sm = a + c, df = a - c;
    float adf = fabsf(df);
    float tb = b + b;
    float ab = fabsf(tb);
    float acmx, acmn;
    if (fabsf(a) > fabsf(c)) { acmx = a; acmn = c; } else { acmx = c; acmn = a; }
    float rt;
    if (adf > ab)      rt = adf * sqrtf(1.f + (ab / adf) * (ab / adf));
    else if (adf < ab) rt = ab * sqrtf(1.f + (adf / ab) * (adf / ab));
    else               rt = ab * sqrtf(2.f);
    int sgn1;
    if (sm < 0.f)      { rt1 = 0.5f * (sm - rt); sgn1 = -1; rt2 = (acmx / rt1) * acmn - (b / rt1) * b; }
    else if (sm > 0.f) { rt1 = 0.5f * (sm + rt); sgn1 = 1;  rt2 = (acmx / rt1) * acmn - (b / rt1) * b; }
    else               { rt1 = 0.5f * rt; rt2 = -0.5f * rt; sgn1 = 1; }
    float cs; int sgn2;
    if (df >= 0.f) { cs = df + rt; sgn2 = 1; } else { cs = df - rt; sgn2 = -1; }
    float acs = fabsf(cs);
    if (acs > ab) {
        float ct = -tb / cs;
        sn1 = 1.f / sqrtf(1.f + ct * ct);
        cs1 = ct * sn1;
    } else {
        if (ab == 0.f) { cs1 = 1.f; sn1 = 0.f; }
        else {
            float tn = -cs / tb;
            cs1 = 1.f / sqrtf(1.f + tn * tn);
            sn1 = tn * cs1;
        }
    }
    if (sgn1 == sgn2) { float tn = cs1; cs1 = -sn1; sn1 = tn; }
}

// ---------------------------------------------------------------------------
// K23: phase 1 = gram (256 threads), phase 2 = eig (warp 0 only).
// d/e in shared arrays; all scalar updates are warp-uniform stores.
// ---------------------------------------------------------------------------
__global__ void __launch_bounds__(256) k23(const float* __restrict__ wts,
                                           const float* __restrict__ bias,
                                           float* __restrict__ out) {
    __shared__ float sS[256];
    __shared__ float sH[256];
    __shared__ float sW[512];
    __shared__ float sG[256];
    __shared__ float A[16][17];
    __shared__ float Z[32][17];   // rows 16-31 scratch: all lanes rotate unconditionally
    __shared__ float sd[33];      // d[0..15]; pad for lane-indexed scans
    __shared__ float se[33];      // e[0..14]; pad + scratch slot 20
    __shared__ float stau[16];
    int t = threadIdx.x;
    int slot = blockIdx.x;              // b*32 + o
    int b = slot >> 5, o = slot & 31;

    // ---------------- phase 1: gram ----------------
    {
        int r = t >> 4, c = t & 15;
        int i = r >> 2, k = r & 3;
        int cb = c & ~3, km = c & 3;
        sW[t]       = wts[(((t >> 4)     ) * 32 + o) * 16 + (t & 15)];
        sW[t + 256] = wts[(((t >> 4) + 16) * 32 + o) * 16 + (t & 15)];
        const float* p0 = g_Sp + (size_t)(b * 32) * 1024 + t;
        float pre = ((p0[0] + p0[256]) + p0[512]) + p0[768];
        float g = 0.f;
        for (int l = 0; l < 32; ++l) {
            sS[t] = pre;
            __syncthreads();
            if (l < 31) {
                const float* pn = g_Sp + (size_t)(b * 32 + l + 1) * 1024 + t;
                pre = ((pn[0] + pn[256]) + pn[512]) + pn[768];
            }
            const float* wv = &sW[l * 16];
            float h = 0.f;
#pragma unroll
            for (int j = 0; j < 4; ++j) h = fmaf(sS[r * 16 + cb + j], wv[j * 4 + km], h);
            sH[t] = h;
            __syncthreads();
#pragma unroll
            for (int j = 0; j < 4; ++j) g = fmaf(wv[j * 4 + k], sH[(i * 4 + j) * 16 + c], g);
        }
        sG[t] = g;
        __syncthreads();
    }
    if (t >= 32) return;

    // ---------------- phase 2: eig on warp 0 ----------------
    int lane = t;
    int lr = lane & 15;
    float tr;
    {
        float trp = 0.f;
        if (lane < 16) trp = sG[lane * 17];
        tr = wsum(trp);
    }
    if (lane < 16) {
#pragma unroll
        for (int j = 0; j < 16; ++j) A[lane][j] = 0.5f * (sG[lane * 16 + j] + sG[j * 16 + lane]);
    }
#pragma unroll
    for (int j = 0; j < 16; ++j) Z[lane][j] = (lane == j) ? 1.f : 0.f;
    sd[lane] = 0.f; se[lane] = 0.f;
    if (lane == 0) { sd[32] = 0.f; se[32] = 0.f; }
    __syncwarp();

    // ---- ssytrd (UPLO='L', unblocked) ----
    for (int i = 0; i < 15; ++i) {
        float alpha = A[i + 1][i];
        float colv = (lane >= i + 2 && lane < 16) ? A[lane][i] : 0.f;
        float xnorm = sqrtf(wsum(colv * colv));
        float taui = 0.f, ei = alpha;
        if (i < 14 && xnorm != 0.f) {
            float beta = -copysignf(sqrtf(fmaf(alpha, alpha, xnorm * xnorm)), alpha);
            taui = __fdividef(beta - alpha, beta);
            float sc = __fdividef(1.f, alpha - beta);
            float vlane = colv * sc;
            if (lane == i + 1) vlane = 1.f;
            ei = beta;
            float xr = 0.f;
#pragma unroll
            for (int j = 0; j < 16; ++j) {
                float vj = sget(vlane, j);
                xr = fmaf(A[lr][j], vj, xr);
            }
            xr = (lane >= i + 1 && lane < 16) ? xr * taui : 0.f;
            float dotxv = wsum(xr * vlane);
            float wr = fmaf(-0.5f * taui * dotxv, vlane, xr);
            __syncwarp();
#pragma unroll
            for (int j = 0; j < 16; ++j) {
                float vj = sget(vlane, j), wj = sget(wr, j);
                if (lane >= j && lane < 16) {
                    float val = fmaf(wr, -vj, fmaf(vlane, -wj, A[lane][j]));
                    A[lane][j] = val;
                    if (lane != j) A[j][lane] = val;
                }
            }
            __syncwarp();
            if (lane >= i + 2 && lane < 16) A[lane][i] = vlane;
            __syncwarp();
        }
        se[i] = ei;          // uniform store
        stau[i] = taui;      // uniform store
    }
    if (lane < 16) sd[lane] = A[lane][lane];
    __syncwarp();

    // ---- ssteqr (COMPZ='I') ----
    const float EPS  = 5.9604645e-08f;
    const float EPS2 = 3.5527137e-15f;
    const float SAFMIN = 1.17549435e-38f;
    const float SSFMAX = 3.0744573e18f;
    const float SSFMIN = 3.0517578e-05f;
    int l1 = 0, jtot = 0;
    const int nmaxit = 480;

    while (l1 <= 15) {
        se[(l1 > 0) ? l1 - 1 : 20] = 0.f;
        int m;
        {
            float tst = fabsf(se[lane]);
            bool stop = (lane >= l1 && lane < 15) &&
                (tst == 0.f || tst <= (sqrtf(fabsf(sd[lane])) * sqrtf(fabsf(sd[lane + 1]))) * EPS);
            unsigned msk = __ballot_sync(FULLMASK, stop);
            m = msk ? (__ffs(msk) - 1) : 15;
            se[(m < 15) ? m : 20] = 0.f;
        }
        int l = l1, lsv = l1, lend = m, lendsv = m;
        l1 = m + 1;
        if (lend == l) continue;
        float av = (lane >= l && lane <= lend && lane < 16) ? fabsf(sd[lane]) : 0.f;
        float ae = (lane >= l && lane < lend) ? fabsf(se[lane]) : 0.f;
        float anorm = wmaxf(fmaxf(av, ae));
        if (anorm == 0.f) continue;
        int iscale = 0;
        if (anorm > SSFMAX) {
            iscale = 1; float sc = SSFMAX / anorm;
            if (lane >= l && lane <= lend) sd[lane] *= sc;
            if (lane >= l && lane < lend)  se[lane] *= sc;
            __syncwarp();
        } else if (anorm < SSFMIN) {
            iscale = 2; float sc = SSFMIN / anorm;
            if (lane >= l && lane <= lend) sd[lane] *= sc;
            if (lane >= l && lane < lend)  se[lane] *= sc;
            __syncwarp();
        }
        if (fabsf(sd[lend]) < fabsf(sd[l])) { int tmp = l; l = lend; lend = tmp; }

        if (lend > l) {
            // ---- QL sweeps: scan M = l..lend-1 upward, take lowest ----
            for (;;) {
                int mq;
                {
                    float ev = se[lane];
                    bool stop = (lane >= l && lane < lend) &&
                        (ev * ev <= (EPS2 * fabsf(sd[lane])) * fabsf(sd[lane + 1]) + SAFMIN);
                    unsigned msk = __ballot_sync(FULLMASK, stop);
                    mq = msk ? (__ffs(msk) - 1) : lend;
                }
                se[(mq < lend) ? mq : 20] = 0.f;
                float p = sd[l];
                if (mq == l) { l++; if (l <= lend) continue; break; }
                if (mq == l + 1) {
                    float rt1, rt2, cc, ss;
                    laev2(sd[l], se[l], sd[l + 1], rt1, rt2, cc, ss);
                    float tz = Z[lane][l + 1];
                    Z[lane][l + 1] = cc * tz - ss * Z[lane][l];
                    Z[lane][l]     = ss * tz + cc * Z[lane][l];
                    sd[l] = rt1; sd[l + 1] = rt2; se[l] = 0.f;
                    l += 2; if (l <= lend) continue; break;
                }
                if (jtot >= nmaxit) break;
                jtot++;
                float el = se[l];
                float gg = __fdividef(sd[l + 1] - p, 2.f * el);
                float rr = sqrtf(fmaf(gg, gg, 1.f));
                gg = sd[mq] - p + __fdividef(el, gg + copysignf(rr, gg));
                float ss = 1.f, cc = 1.f; p = 0.f;
                float carry = Z[lane][mq];
                float dI1 = sd[mq];
                for (int i = mq - 1; i >= l; --i) {
                    float eI = se[i];
                    float dI = sd[i];
                    float zlo = Z[lane][i];
                    float ff = ss * eI, bb = cc * eI;
                    lartg(gg, ff, cc, ss, rr);
                    se[(i != mq - 1) ? i + 1 : 20] = rr;
                    gg = dI1 - p;
                    rr = (dI - gg) * ss + 2.f * cc * bb;
                    p = ss * rr;
                    sd[i + 1] = gg + p;
                    gg = cc * rr - bb;
                    Z[lane][i + 1] = fmaf(cc, carry, ss * zlo);
                    carry = fmaf(cc, zlo, -ss * carry);
                    dI1 = dI;
                }
                Z[lane][l] = carry;
                sd[l] = sd[l] - p;
                se[l] = gg;
            }
        } else {
            // ---- QR sweeps: scan M = l..lend+1 DOWNWARD, take HIGHEST ----
            for (;;) {
                int mq;
                {
                    float ev = se[(lane > 0) ? lane - 1 : 20];
                    bool stop = (lane > lend && lane <= l) &&
                        (ev * ev <= (EPS2 * fabsf(sd[lane])) * fabsf(sd[(lane > 0) ? lane - 1 : 20]) + SAFMIN);
                    unsigned msk = __ballot_sync(FULLMASK, stop);
                    mq = msk ? (31 - __clz(msk)) : lend;   // FIXED: highest lane
                }
                se[(mq > lend) ? mq - 1 : 20] = 0.f;
                float p = sd[l];
                if (mq == l) { l--; if (l >= lend) continue; break; }
                if (mq == l - 1) {
                    float rt1, rt2, cc, ss;
                    laev2(sd[l - 1], se[l - 1], sd[l], rt1, rt2, cc, ss);
                    float tz = Z[lane][l];
                    Z[lane][l]     = cc * tz - ss * Z[lane][l - 1];
                    Z[lane][l - 1] = ss * tz + cc * Z[lane][l - 1];
                    sd[l - 1] = rt1; sd[l] = rt2; se[l - 1] = 0.f;
                    l -= 2; if (l >= lend) continue; break;
                }
                if (jtot >= nmaxit) break;
                jtot++;
                float el = se[l - 1];
                float gg = __fdividef(sd[l - 1] - p, 2.f * el);
                float rr = sqrtf(fmaf(gg, gg, 1.f));
                gg = sd[mq] - p + __fdividef(el, gg + copysignf(rr, gg));
                float ss = 1.f, cc = 1.f; p = 0.f;
                float carry = Z[lane][mq];
                float dI = sd[mq];
                for (int i = mq; i < l; ++i) {
                    float eI = se[i];
                    float dI1 = sd[i + 1];
                    float zhi = Z[lane][i + 1];
                    float ff = ss * eI, bb = cc * eI;
                    lartg(gg, ff, cc, ss, rr);
                    se[(i != mq) ? i - 1 : 20] = rr;
                    gg = dI - p;
                    rr = (dI1 - gg) * ss + 2.f * cc * bb;
                    p = ss * rr;
                    sd[i] = gg + p;
                    gg = cc * rr - bb;
                    Z[lane][i] = fmaf(ss, zhi, cc * carry);
                    carry = fmaf(cc, zhi, -ss * carry);
                    dI = dI1;
                }
                Z[lane][l] = carry;
                sd[l] = sd[l] - p;
                se[l - 1] = gg;
            }
        }
        if (iscale == 1) {
            float sc = anorm / SSFMAX;
            if (lane >= lsv && lane <= lendsv) sd[lane] *= sc;
            if (lane >= lsv && lane < lendsv)  se[lane] *= sc;
            __syncwarp();
        } else if (iscale == 2) {
            float sc = anorm / SSFMIN;
            if (lane >= lsv && lane <= lendsv) sd[lane] *= sc;
            if (lane >= lsv && lane < lendsv)  se[lane] *= sc;
            __syncwarp();
        }
    }

    // ---- argmax eigenvalue BEFORE back-transform ----
    float dv = (lane < 16) ? sd[lane] : -3.4e38f;
    int idx = lane;
#pragma unroll
    for (int off = 16; off; off >>= 1) {
        float vo = __shfl_xor_sync(FULLMASK, dv, off);
        int io = __shfl_xor_sync(FULLMASK, idx, off);
        if (vo > dv || (vo == dv && io < idx)) { dv = vo; idx = io; }
    }
    int cmax = idx & 15;
    float lam = sd[cmax];

    // ---- sormtr on the single needed column ----
    float v16 = Z[lane][cmax];
    for (int i = 14; i >= 0; --i) {
        float ti = stau[i];
        if (ti != 0.f) {
            float vlane = (lane == i + 1) ? 1.f
                        : ((lane >= i + 2 && lane < 16) ? A[lane][i] : 0.f);
            float wj = wsum(vlane * v16) * ti;
            v16 = fmaf(-vlane, wj, v16);
        }
    }

    if (lane == 0) out[slot] = 1.f / (1.f + expf(-(lam / tr - bias[o])));
    if (lane < 16) out[512 + slot * 16 + lane] = v16;
}

// ---------------------------------------------------------------------------
extern "C" void kernel_launch(void* const* d_in, const int* in_sizes, int n_in,
                              void* d_out, int out_size) {
    const float* in   = (const float*)d_in[0];
    const float* wts  = (const float*)d_in[1];
    const float* bias = (const float*)d_in[2];
    float* out = (float*)d_out;
    k1a<<<2048, 256>>>(in);
    k23<<<512, 256>>>(wts, bias, out);
}

// round 17
// speedup vs baseline: 1.0928x; 1.0928x over previous
// SpectralCapsules R17: R14 base + branchless (select-form) lartg ONLY.
// lartg's if/else-if/else was the one un-isolated BSSY/BSYNC source on the
// serial chain (~140c/rotation). Selected values bit-identical to branch form.
#include <cuda_runtime.h>
#include <math.h>

#define FULLMASK 0xffffffffu

constexpr int Bb = 16;    // batch
constexpr int Mm = 256;   // H*W
constexpr int Cc = 544;   // channels = L*(P+1)

__device__ float g_Sp[Bb * 32 * 4 * 256]; // partial S per m-chunk

// ---------------------------------------------------------------------------
// K1a: partial S over 64 m per block (unchanged R8).
// ---------------------------------------------------------------------------
__global__ void __launch_bounds__(256) k1a(const float* __restrict__ in) {
    int blk = blockIdx.x;               // ((b*32+l)*4 + chunk)
    int chunk = blk & 3;
    int bl = blk >> 2;
    int b = bl >> 5, l = bl & 31;
    __shared__ float sp[64 * 16];
    __shared__ float sa2[64];
    __shared__ float red[4][16 * 17];
    int t = threadIdx.x;
    const float* base = in + (size_t)b * Mm * Cc + (size_t)chunk * 64 * Cc;
    {
        int mm = t >> 2, q = t & 3;
        const float4* src = (const float4*)(base + (size_t)mm * Cc + l * 16) + q;
        ((float4*)sp)[mm * 4 + q] = *src;
    }
    if (t < 64) {
        float a = base[(size_t)t * Cc + 512 + l];
        sa2[t] = a * a;
    }
    __syncthreads();
    int g = t >> 6, u = t & 63;
    int r0 = (u >> 3) * 2, c0 = (u & 7) * 2;
    float a00 = 0.f, a01 = 0.f, a10 = 0.f, a11 = 0.f;
#pragma unroll
    for (int mm = 0; mm < 16; ++mm) {
        int m = g * 16 + mm;
        float a2 = sa2[m];
        float2 vr = *(const float2*)&sp[m * 16 + r0];
        float2 vc = *(const float2*)&sp[m * 16 + c0];
        float t0 = a2 * vr.x, t1 = a2 * vr.y;
        a00 = fmaf(t0, vc.x, a00);
        a01 = fmaf(t0, vc.y, a01);
        a10 = fmaf(t1, vc.x, a10);
        a11 = fmaf(t1, vc.y, a11);
    }
    red[g][r0 * 17 + c0]           = a00;
    red[g][r0 * 17 + c0 + 1]       = a01;
    red[g][(r0 + 1) * 17 + c0]     = a10;
    red[g][(r0 + 1) * 17 + c0 + 1] = a11;
    __syncthreads();
    {
        int r = t >> 4, c = t & 15;
        int idx = r * 17 + c;
        g_Sp[blk * 256 + t] = ((red[0][idx] + red[1][idx]) + red[2][idx]) + red[3][idx];
    }
}

// ---------------------------------------------------------------------------
// helpers
// ---------------------------------------------------------------------------
__device__ __forceinline__ float wsum(float x) {
#pragma unroll
    for (int o = 16; o; o >>= 1) x += __shfl_xor_sync(FULLMASK, x, o);
    return x;
}
__device__ __forceinline__ float wmaxf(float x) {
#pragma unroll
    for (int o = 16; o; o >>= 1) x = fmaxf(x, __shfl_xor_sync(FULLMASK, x, o));
    return x;
}
__device__ __forceinline__ float sget(float v, int i) {
    return __shfl_sync(FULLMASK, v, i);
}
#define SSET(var, idx, val) do { float _v = (val); int _i = (idx); \
    if ((threadIdx.x & 31) == _i) var = _v; } while (0)
#define SSETC(var, idx, val, cond) do { float _v = (val); int _i = (idx); \
    bool _c = (cond); if (((threadIdx.x & 31) == _i) & _c) var = _v; } while (0)

// Branchless lartg: general path unconditional; special cases via SEL.
// Selected values identical to the branch form (incl. f==0&&g==0 -> c=1,s=0,r=0).
// NaN/Inf in the discarded general path is harmless under SEL.
__device__ __forceinline__ void lartg(float f, float g, float& c, float& s, float& r) {
    float t2 = fmaf(f, f, g * g);
    float rinv = rsqrtf(t2);
    float cg = fabsf(f) * rinv;
    float rg = copysignf(t2 * rinv, f);
    float sg = g * rinv * copysignf(1.f, f);
    bool gz = (g == 0.f);
    bool fz = (f == 0.f);
    c = gz ? 1.f : (fz ? 0.f               : cg);
    s = gz ? 0.f : (fz ? copysignf(1.f, g) : sg);
    r = gz ? f   : (fz ? fabsf(g)          : rg);
}

__device__ __forceinline__ void laev2(float a, float b, float c,
                                      float& rt1, float& rt2, float& cs1, float& sn1) {
    float sm = a + c, df = a - c;
    float adf = fabsf(df);
    float tb = b + b;
    float ab = fabsf(tb);
    float acmx, acmn;
    if (fabsf(a) > fabsf(c)) { acmx = a; acmn = c; } else { acmx = c; acmn = a; }
    float rt;
    if (adf > ab)      rt = adf * sqrtf(1.f + (ab / adf) * (ab / adf));
    else if (adf < ab) rt = ab * sqrtf(1.f + (adf / ab) * (adf / ab));
    else               rt = ab * sqrtf(2.f);
    int sgn1;
    if (sm < 0.f)      { rt1 = 0.5f * (sm - rt); sgn1 = -1; rt2 = (acmx / rt1) * acmn - (b / rt1) * b; }
    else if (sm > 0.f) { rt1 = 0.5f * (sm + rt); sgn1 = 1;  rt2 = (acmx / rt1) * acmn - (b / rt1) * b; }
    else               { rt1 = 0.5f * rt; rt2 = -0.5f * rt; sgn1 = 1; }
    float cs; int sgn2;
    if (df >= 0.f) { cs = df + rt; sgn2 = 1; } else { cs = df - rt; sgn2 = -1; }
    float acs = fabsf(cs);
    if (acs > ab) {
        float ct = -tb / cs;
        sn1 = 1.f / sqrtf(1.f + ct * ct);
        cs1 = ct * sn1;
    } else {
        if (ab == 0.f) { cs1 = 1.f; sn1 = 0.f; }
        else {
            float tn = -cs / tb;
            cs1 = 1.f / sqrtf(1.f + tn * tn);
            sn1 = tn * cs1;
        }
    }
    if (sgn1 == sgn2) { float tn = cs1; cs1 = -sn1; sn1 = tn; }
}

// ---------------------------------------------------------------------------
// K23: phase 1 = gram (256 threads), phase 2 = eig (warp 0 only).
// ---------------------------------------------------------------------------
__global__ void __launch_bounds__(256) k23(const float* __restrict__ wts,
                                           const float* __restrict__ bias,
                                           float* __restrict__ out) {
    __shared__ float sS[256];
    __shared__ float sH[256];
    __shared__ float sW[512];
    __shared__ float sG[256];
    __shared__ float A[16][17];
    __shared__ float Z[32][17];   // rows 16-31 scratch: all lanes rotate unconditionally
    int t = threadIdx.x;
    int slot = blockIdx.x;              // b*32 + o
    int b = slot >> 5, o = slot & 31;

    // ---------------- phase 1: gram ----------------
    {
        int r = t >> 4, c = t & 15;
        int i = r >> 2, k = r & 3;
        int cb = c & ~3, km = c & 3;
        sW[t]       = wts[(((t >> 4)     ) * 32 + o) * 16 + (t & 15)];
        sW[t + 256] = wts[(((t >> 4) + 16) * 32 + o) * 16 + (t & 15)];
        const float* p0 = g_Sp + (size_t)(b * 32) * 1024 + t;
        float pre = ((p0[0] + p0[256]) + p0[512]) + p0[768];
        float g = 0.f;
        for (int l = 0; l < 32; ++l) {
            sS[t] = pre;
            __syncthreads();
            if (l < 31) {
                const float* pn = g_Sp + (size_t)(b * 32 + l + 1) * 1024 + t;
                pre = ((pn[0] + pn[256]) + pn[512]) + pn[768];
            }
            const float* wv = &sW[l * 16];
            float h = 0.f;
#pragma unroll
            for (int j = 0; j < 4; ++j) h = fmaf(sS[r * 16 + cb + j], wv[j * 4 + km], h);
            sH[t] = h;
            __syncthreads();
#pragma unroll
            for (int j = 0; j < 4; ++j) g = fmaf(wv[j * 4 + k], sH[(i * 4 + j) * 16 + c], g);
        }
        sG[t] = g;
        __syncthreads();
    }
    if (t >= 32) return;

    // ---------------- phase 2: eig on warp 0 ----------------
    int lane = t;
    int lr = lane & 15;
    float tr;
    {
        float trp = 0.f;
        if (lane < 16) trp = sG[lane * 17];
        tr = wsum(trp);
    }
    if (lane < 16) {
#pragma unroll
        for (int j = 0; j < 16; ++j) A[lane][j] = 0.5f * (sG[lane * 16 + j] + sG[j * 16 + lane]);
    }
#pragma unroll
    for (int j = 0; j < 16; ++j) Z[lane][j] = (lane == j) ? 1.f : 0.f;
    __syncwarp();

    float dreg = 0.f, ereg = 0.f, taureg = 0.f;

    // ---- ssytrd (UPLO='L', unblocked) ----
    for (int i = 0; i < 15; ++i) {
        float alpha = A[i + 1][i];
        float colv = (lane >= i + 2 && lane < 16) ? A[lane][i] : 0.f;
        float xnorm = sqrtf(wsum(colv * colv));
        float taui = 0.f, ei = alpha;
        if (i < 14 && xnorm != 0.f) {
            float beta = -copysignf(sqrtf(fmaf(alpha, alpha, xnorm * xnorm)), alpha);
            taui = __fdividef(beta - alpha, beta);
            float sc = __fdividef(1.f, alpha - beta);
            float vlane = colv * sc;
            if (lane == i + 1) vlane = 1.f;
            ei = beta;
            float xr = 0.f;
#pragma unroll
            for (int j = 0; j < 16; ++j) {
                float vj = sget(vlane, j);
                xr = fmaf(A[lr][j], vj, xr);
            }
            xr = (lane >= i + 1 && lane < 16) ? xr * taui : 0.f;
            float dotxv = wsum(xr * vlane);
            float wr = fmaf(-0.5f * taui * dotxv, vlane, xr);
            __syncwarp();
#pragma unroll
            for (int j = 0; j < 16; ++j) {
                float vj = sget(vlane, j), wj = sget(wr, j);
                if (lane >= j && lane < 16) {
                    float val = fmaf(wr, -vj, fmaf(vlane, -wj, A[lane][j]));
                    A[lane][j] = val;
                    if (lane != j) A[j][lane] = val;
                }
            }
            __syncwarp();
            if (lane >= i + 2 && lane < 16) A[lane][i] = vlane;
            __syncwarp();
        }
        SSET(ereg, i, ei);
        SSET(taureg, i, taui);
    }
    if (lane < 16) dreg = A[lane][lane];

    // ---- ssteqr (COMPZ='I') ----
    const float EPS  = 5.9604645e-08f;
    const float EPS2 = 3.5527137e-15f;
    const float SAFMIN = 1.17549435e-38f;
    const float SSFMAX = 3.0744573e18f;
    const float SSFMIN = 3.0517578e-05f;
    int l1 = 0, jtot = 0;
    const int nmaxit = 480;

    while (l1 <= 15) {
        SSETC(ereg, l1 - 1, 0.f, l1 > 0);
        int m;
        {
            float dnext = __shfl_down_sync(FULLMASK, dreg, 1);
            float tst = fabsf(ereg);
            bool stop = (lane >= l1 && lane < 15) &&
                (tst == 0.f || tst <= (sqrtf(fabsf(dreg)) * sqrtf(fabsf(dnext))) * EPS);
            unsigned msk = __ballot_sync(FULLMASK, stop);
            m = msk ? (__ffs(msk) - 1) : 15;
            SSETC(ereg, m, 0.f, m < 15);
        }
        int l = l1, lsv = l1, lend = m, lendsv = m;
        l1 = m + 1;
        if (lend == l) continue;
        float av = (lane >= l && lane <= lend && lane < 16) ? fabsf(dreg) : 0.f;
        float ae = (lane >= l && lane < lend) ? fabsf(ereg) : 0.f;
        float anorm = wmaxf(fmaxf(av, ae));
        if (anorm == 0.f) continue;
        int iscale = 0;
        if (anorm > SSFMAX) {
            iscale = 1; float sc = SSFMAX / anorm;
            if (lane >= l && lane <= lend) dreg *= sc;
            if (lane >= l && lane < lend)  ereg *= sc;
        } else if (anorm < SSFMIN) {
            iscale = 2; float sc = SSFMIN / anorm;
            if (lane >= l && lane <= lend) dreg *= sc;
            if (lane >= l && lane < lend)  ereg *= sc;
        }
        if (fabsf(sget(dreg, lend)) < fabsf(sget(dreg, l))) { int tmp = l; l = lend; lend = tmp; }

        if (lend > l) {
            // ---- QL sweeps ----
            for (;;) {
                int mq;
                {
                    float dnext = __shfl_down_sync(FULLMASK, dreg, 1);
                    bool stop = (lane >= l && lane < lend) &&
                        (ereg * ereg <= (EPS2 * fabsf(dreg)) * fabsf(dnext) + SAFMIN);
                    unsigned msk = __ballot_sync(FULLMASK, stop);
                    mq = msk ? (__ffs(msk) - 1) : lend;
                }
                SSETC(ereg, mq, 0.f, mq < lend);
                float p = sget(dreg, l);
                if (mq == l) { l++; if (l <= lend) continue; break; }
                if (mq == l + 1) {
                    float rt1, rt2, cc, ss;
                    laev2(sget(dreg, l), sget(ereg, l), sget(dreg, l + 1), rt1, rt2, cc, ss);
                    float tz = Z[lane][l + 1];
                    Z[lane][l + 1] = cc * tz - ss * Z[lane][l];
                    Z[lane][l]     = ss * tz + cc * Z[lane][l];
                    SSET(dreg, l, rt1); SSET(dreg, l + 1, rt2); SSET(ereg, l, 0.f);
                    l += 2; if (l <= lend) continue; break;
                }
                if (jtot >= nmaxit) break;
                jtot++;
                float el = sget(ereg, l);
                float gg = __fdividef(sget(dreg, l + 1) - p, 2.f * el);
                float rr = sqrtf(fmaf(gg, gg, 1.f));
                gg = sget(dreg, mq) - p + __fdividef(el, gg + copysignf(rr, gg));
                float ss = 1.f, cc = 1.f; p = 0.f;
                float carry = Z[lane][mq];
                float dI1 = sget(dreg, mq);
                for (int i = mq - 1; i >= l; --i) {
                    float eI = sget(ereg, i);
                    float dI = sget(dreg, i);
                    float zlo = Z[lane][i];
                    float ff = ss * eI, bb = cc * eI;
                    lartg(gg, ff, cc, ss, rr);
                    SSETC(ereg, i + 1, rr, i != mq - 1);
                    gg = dI1 - p;
                    rr = (dI - gg) * ss + 2.f * cc * bb;
                    p = ss * rr;
                    SSET(dreg, i + 1, gg + p);
                    gg = cc * rr - bb;
                    Z[lane][i + 1] = fmaf(cc, carry, ss * zlo);
                    carry = fmaf(cc, zlo, -ss * carry);
                    dI1 = dI;
                }
                Z[lane][l] = carry;
                SSET(dreg, l, sget(dreg, l) - p);
                SSET(ereg, l, gg);
            }
        } else {
            // ---- QR sweeps ----
            for (;;) {
                int mq;
                {
                    float dnext = __shfl_down_sync(FULLMASK, dreg, 1);
                    bool stop = (lane >= lend && lane < l) &&
                        (ereg * ereg <= (EPS2 * fabsf(dnext)) * fabsf(dreg) + SAFMIN);
                    unsigned msk = __ballot_sync(FULLMASK, stop);
                    mq = msk ? (31 - __clz(msk)) + 1 : lend;
                }
                SSETC(ereg, mq - 1, 0.f, mq > lend);
                float p = sget(dreg, l);
                if (mq == l) { l--; if (l >= lend) continue; break; }
                if (mq == l - 1) {
                    float rt1, rt2, cc, ss;
                    laev2(sget(dreg, l - 1), sget(ereg, l - 1), sget(dreg, l), rt1, rt2, cc, ss);
                    float tz = Z[lane][l];
                    Z[lane][l]     = cc * tz - ss * Z[lane][l - 1];
                    Z[lane][l - 1] = ss * tz + cc * Z[lane][l - 1];
                    SSET(dreg, l - 1, rt1); SSET(dreg, l, rt2); SSET(ereg, l - 1, 0.f);
                    l -= 2; if (l >= lend) continue; break;
                }
                if (jtot >= nmaxit) break;
                jtot++;
                float el = sget(ereg, l - 1);
                float gg = __fdividef(sget(dreg, l - 1) - p, 2.f * el);
                float rr = sqrtf(fmaf(gg, gg, 1.f));
                gg = sget(dreg, mq) - p + __fdividef(el, gg + copysignf(rr, gg));
                float ss = 1.f, cc = 1.f; p = 0.f;
                float carry = Z[lane][mq];
                float dI = sget(dreg, mq);
                for (int i = mq; i < l; ++i) {
                    float eI = sget(ereg, i);
                    float dI1 = sget(dreg, i + 1);
                    float zhi = Z[lane][i + 1];
                    float ff = ss * eI, bb = cc * eI;
                    lartg(gg, ff, cc, ss, rr);
                    SSETC(ereg, i - 1, rr, i != mq);
                    gg = dI - p;
                    rr = (dI1 - gg) * ss + 2.f * cc * bb;
                    p = ss * rr;
                    SSET(dreg, i, gg + p);
                    gg = cc * rr - bb;
                    Z[lane][i] = fmaf(ss, zhi, cc * carry);
                    carry = fmaf(cc, zhi, -ss * carry);
                    dI = dI1;
                }
                Z[lane][l] = carry;
                SSET(dreg, l, sget(dreg, l) - p);
                SSET(ereg, l - 1, gg);
            }
        }
        if (iscale == 1) {
            float sc = anorm / SSFMAX;
            if (lane >= lsv && lane <= lendsv) dreg *= sc;
            if (lane >= lsv && lane < lendsv)  ereg *= sc;
        } else if (iscale == 2) {
            float sc = anorm / SSFMIN;
            if (lane >= lsv && lane <= lendsv) dreg *= sc;
            if (lane >= lsv && lane < lendsv)  ereg *= sc;
        }
    }

    // ---- argmax eigenvalue BEFORE back-transform ----
    float dv = (lane < 16) ? dreg : -3.4e38f;
    int idx = lane;
#pragma unroll
    for (int off = 16; off; off >>= 1) {
        float vo = __shfl_xor_sync(FULLMASK, dv, off);
        int io = __shfl_xor_sync(FULLMASK, idx, off);
        if (vo > dv || (vo == dv && io < idx)) { dv = vo; idx = io; }
    }
    int cmax = idx & 15;   // safety clamp
    float lam = sget(dreg, cmax);

    // ---- sormtr on the single needed column ----
    float v16 = Z[lane][cmax];
    for (int i = 14; i >= 0; --i) {
        float ti = sget(taureg, i);
        if (ti != 0.f) {
            float vlane = (lane == i + 1) ? 1.f
                        : ((lane >= i + 2 && lane < 16) ? A[lane][i] : 0.f);
            float wj = wsum(vlane * v16) * ti;
            v16 = fmaf(-vlane, wj, v16);
        }
    }

    if (lane == 0) out[slot] = 1.f / (1.f + expf(-(lam / tr - bias[o])));
    if (lane < 16) out[512 + slot * 16 + lane] = v16;
}

// ---------------------------------------------------------------------------
extern "C" void kernel_launch(void* const* d_in, const int* in_sizes, int n_in,
                              void* d_out, int out_size) {
    const float* in   = (const float*)d_in[0];
    const float* wts  = (const float*)d_in[1];
    const float* bias = (const float*)d_in[2];
    float* out = (float*)d_out;
    k1a<<<2048, 256>>>(in);
    k23<<<512, 256>>>(wts, bias, out);
}